// round 15
// baseline (speedup 1.0000x reference)
#include <cuda_runtime.h>

#define BATCH        16384
#define NUM_FIELDS   20
#define NUM_FEATURES 100000
#define LATENT_DIM   64

// R7 operating point + warp-parity burst staggering.
// Two samples per warp (one per half-warp); each lane owns 4 of 64 dims ->
// one LDG.128 per embedding row; 20 gathers in two bursts of 10.
// NEW: odd warps process burst B (fields 10..19) first, even warps burst A
// (fields 0..9) first. Co-resident warps' LDG bursts and drain points then
// interleave instead of aligning, lowering the instantaneous L1tex
// wavefront-queue depth per SM at zero instruction cost.
__device__ __forceinline__ void gather_burst(
    const float* __restrict__ emb, int xi0, int xi1,
    int base /* 0 or 10 */, int lh,
    float4& sv, float& sq)
{
    float4 buf[10];
    #pragma unroll
    for (int j = 0; j < 10; ++j) {
        const int f = base + j;
        int idx;
        if (f < 16) idx = __shfl_sync(0xffffffffu, xi0, f, 16);
        else        idx = __shfl_sync(0xffffffffu, xi1, f - 16, 16);
        const float4* row = reinterpret_cast<const float4*>(
            emb + ((size_t)f * NUM_FEATURES + (size_t)idx) * LATENT_DIM);
        buf[j] = __ldg(row + lh);
    }
    #pragma unroll
    for (int j = 0; j < 10; ++j) {
        const float4 v = buf[j];
        sv.x += v.x;  sv.y += v.y;  sv.z += v.z;  sv.w += v.w;
        sq = fmaf(v.x, v.x, sq);  sq = fmaf(v.y, v.y, sq);
        sq = fmaf(v.z, v.z, sq);  sq = fmaf(v.w, v.w, sq);
    }
}

__global__ __launch_bounds__(256)
void ffm_kernel(const int* __restrict__ x,
                const float* __restrict__ emb,
                float* __restrict__ out)
{
    const int gwarp = (blockIdx.x * blockDim.x + threadIdx.x) >> 5;
    const int lane  = threadIdx.x & 31;
    const int half  = lane >> 4;          // sample within the warp
    const int lh    = lane & 15;          // lane within half-warp
    const int s     = gwarp * 2 + half;   // batch sample id
    if (s >= BATCH) return;

    // 20 indices per half-warp: lanes 0..15 hold fields 0..15,
    // lanes 0..3 additionally hold fields 16..19.
    const int* xrow = x + s * NUM_FIELDS;
    int xi0 = __ldg(xrow + lh);                                    // fields 0..15
    int xi1 = (lh < NUM_FIELDS - 16) ? __ldg(xrow + 16 + lh) : 0;  // fields 16..19

    float4 sv = make_float4(0.f, 0.f, 0.f, 0.f);   // partial of sum_f V[f]
    float  sq = 0.f;                               // partial of sum V^2

    // Warp-parity stagger: even warps do fields [0..9] then [10..19];
    // odd warps the reverse. Sum is field-order independent.
    const int first  = (gwarp & 1) ? 10 : 0;
    const int second = 10 - first;

    gather_burst(emb, xi0, xi1, first, lh, sv, sq);
    // Keep the second burst's LDGs from being hoisted into the first.
    asm volatile("" ::: "memory");
    gather_burst(emb, xi0, xi1, second, lh, sv, sq);

    float part = fmaf(sv.x, sv.x, fmaf(sv.y, sv.y,
                 fmaf(sv.z, sv.z, sv.w * sv.w))) - sq;
    int   lin  = xi0 + xi1;

    // Reduce within the 16-lane half-warp.
    #pragma unroll
    for (int o = 8; o > 0; o >>= 1) {
        part += __shfl_xor_sync(0xffffffffu, part, o);
        lin  += __shfl_xor_sync(0xffffffffu, lin,  o);
    }

    if (lh == 0)
        out[s] = (float)lin + 0.5f * part;
}

extern "C" void kernel_launch(void* const* d_in, const int* in_sizes, int n_in,
                              void* d_out, int out_size)
{
    const int*   x   = (const int*)d_in[0];     // (16384, 20) int32
    // d_in[1] = field_indices (arange(20)) — identity, unused
    const float* emb = (const float*)d_in[2];   // (20, 100000, 64) fp32
    float*       out = (float*)d_out;           // (16384,) fp32

    const int threads = 256;                    // 8 warps = 16 samples / block
    const int warps   = (BATCH + 1) / 2;        // 8192 warps
    const int blocks  = (warps * 32 + threads - 1) / threads;  // 1024
    ffm_kernel<<<blocks, threads>>>(x, emb, out);
}

// round 16
// speedup vs baseline: 1.7413x; 1.7413x over previous
#include <cuda_runtime.h>

#define BATCH        16384
#define NUM_FIELDS   20
#define NUM_FEATURES 100000
#define LATENT_DIM   64

// FINAL — R7 operating point, the measured optimum over 15 rounds.
// - Two samples per warp, one per half-warp (16 lanes each).
// - Each lane owns 4 of the 64 dims -> one LDG.128 (__ldg) per embedding row;
//   each row read is 16 lanes x 16 B = 256 B fully coalesced.
// - 8192 warps (1024 x 256-thr blocks) = one resident wave (~55 warps/SM),
//   regs=32 (full RF). COMPILE-TIME-CONSTANT field numbering everywhere —
//   runtime burst bases (R15) blew registers to 90 and tanked occupancy.
// - 20 gathers issue as TWO bursts of 10 with a scheduling barrier between:
//   front-batch depth 20 -> 10 cuts cross-CTA L1tex wavefront-queue
//   contention and the end-of-kernel straggler spread.
// Measured: 10.72us = 7.84 TB/s effective on 84 MB of random 256-B gathers
// (~98% of HBM spec, partially warm-L2 across graph replays). Rejected:
// 4 smp/warp (12.8), LDG.256 (13.1), 1 smp/warp 2-field (12.3), 128-thr
// blocks (10.9), 4x5 bursts (tie), software pipelining (tie), evict_last
// (neutral), __ldcg (11.0), runtime-staggered bursts (19.2).
__global__ __launch_bounds__(256)
void ffm_kernel(const int* __restrict__ x,
                const float* __restrict__ emb,
                float* __restrict__ out)
{
    const int gwarp = (blockIdx.x * blockDim.x + threadIdx.x) >> 5;
    const int lane  = threadIdx.x & 31;
    const int half  = lane >> 4;          // sample within the warp
    const int lh    = lane & 15;          // lane within half-warp
    const int s     = gwarp * 2 + half;   // batch sample id
    if (s >= BATCH) return;

    // 20 indices per half-warp: lanes 0..15 hold fields 0..15,
    // lanes 0..3 additionally hold fields 16..19.
    const int* xrow = x + s * NUM_FIELDS;
    int xi0 = __ldg(xrow + lh);                                    // fields 0..15
    int xi1 = (lh < NUM_FIELDS - 16) ? __ldg(xrow + 16 + lh) : 0;  // fields 16..19

    float4 sv = make_float4(0.f, 0.f, 0.f, 0.f);   // partial of sum_f V[f]
    float  sq = 0.f;                               // partial of sum V^2

    // ---- Burst 1: fields 0..9 ----
    float4 g1[10];
    #pragma unroll
    for (int f = 0; f < 10; ++f) {
        const int idx = __shfl_sync(0xffffffffu, xi0, f, 16);
        const float4* row = reinterpret_cast<const float4*>(
            emb + ((size_t)f * NUM_FEATURES + (size_t)idx) * LATENT_DIM);
        g1[f] = __ldg(row + lh);
    }
    #pragma unroll
    for (int f = 0; f < 10; ++f) {
        const float4 v = g1[f];
        sv.x += v.x;  sv.y += v.y;  sv.z += v.z;  sv.w += v.w;
        sq = fmaf(v.x, v.x, sq);  sq = fmaf(v.y, v.y, sq);
        sq = fmaf(v.z, v.z, sq);  sq = fmaf(v.w, v.w, sq);
    }

    // Prevent ptxas from hoisting burst-2 LDGs above burst-1 consumption.
    asm volatile("" ::: "memory");

    // ---- Burst 2: fields 10..19 ----
    float4 g2[10];
    #pragma unroll
    for (int f = 10; f < NUM_FIELDS; ++f) {
        int idx;
        if (f < 16) idx = __shfl_sync(0xffffffffu, xi0, f, 16);
        else        idx = __shfl_sync(0xffffffffu, xi1, f - 16, 16);
        const float4* row = reinterpret_cast<const float4*>(
            emb + ((size_t)f * NUM_FEATURES + (size_t)idx) * LATENT_DIM);
        g2[f - 10] = __ldg(row + lh);
    }
    #pragma unroll
    for (int f = 0; f < 10; ++f) {
        const float4 v = g2[f];
        sv.x += v.x;  sv.y += v.y;  sv.z += v.z;  sv.w += v.w;
        sq = fmaf(v.x, v.x, sq);  sq = fmaf(v.y, v.y, sq);
        sq = fmaf(v.z, v.z, sq);  sq = fmaf(v.w, v.w, sq);
    }

    float part = fmaf(sv.x, sv.x, fmaf(sv.y, sv.y,
                 fmaf(sv.z, sv.z, sv.w * sv.w))) - sq;
    int   lin  = xi0 + xi1;

    // Reduce within the 16-lane half-warp.
    #pragma unroll
    for (int o = 8; o > 0; o >>= 1) {
        part += __shfl_xor_sync(0xffffffffu, part, o);
        lin  += __shfl_xor_sync(0xffffffffu, lin,  o);
    }

    if (lh == 0)
        out[s] = (float)lin + 0.5f * part;
}

extern "C" void kernel_launch(void* const* d_in, const int* in_sizes, int n_in,
                              void* d_out, int out_size)
{
    const int*   x   = (const int*)d_in[0];     // (16384, 20) int32
    // d_in[1] = field_indices (arange(20)) — identity, unused
    const float* emb = (const float*)d_in[2];   // (20, 100000, 64) fp32
    float*       out = (float*)d_out;           // (16384,) fp32

    const int threads = 256;                    // 8 warps = 16 samples / block
    const int warps   = (BATCH + 1) / 2;        // 8192 warps
    const int blocks  = (warps * 32 + threads - 1) / threads;  // 1024
    ffm_kernel<<<blocks, threads>>>(x, emb, out);
}

// round 17
// speedup vs baseline: 1.7881x; 1.0269x over previous
#include <cuda_runtime.h>

#define BATCH        16384
#define NUM_FIELDS   20
#define NUM_FEATURES 100000
#define LATENT_DIM   64

// FINAL — R7 operating point, measured optimum over 16 rounds (benched
// 10.72us x3, 11.01us x1; run-to-run noise is +/-0.3us).
// - Two samples per warp, one per half-warp (16 lanes each).
// - Each lane owns 4 of the 64 dims -> one LDG.128 (__ldg) per embedding row;
//   each row read is 16 lanes x 16 B = 256 B fully coalesced.
// - 8192 warps (1024 x 256-thr blocks) = one resident wave (~55 warps/SM),
//   regs=32 (full RF). All field numbering compile-time constant (runtime
//   burst bases blow registers to 90 and tank occupancy — measured).
// - 20 gathers issue as TWO bursts of 10 with a scheduling barrier between:
//   front-batch depth 20 -> 10 cuts cross-CTA L1tex wavefront-queue
//   contention and the end-of-kernel straggler spread.
// 84 MB of random 256-B gathers at ~7.8 TB/s effective (~98% of HBM spec,
// partially warm-L2 across CUDA-graph replays). Probed and rejected:
// 1 smp/warp float2 (13.3), 4 smp/warp (12.8), LDG.256 (13.1), 1 smp/warp
// 2-field (12.3), 128-thr blocks (10.9), 4x5 bursts (tie), software
// pipelining (tie), evict_last (tie), __ldcg (11.0), staggered bursts (19.2).
__global__ __launch_bounds__(256)
void ffm_kernel(const int* __restrict__ x,
                const float* __restrict__ emb,
                float* __restrict__ out)
{
    const int gwarp = (blockIdx.x * blockDim.x + threadIdx.x) >> 5;
    const int lane  = threadIdx.x & 31;
    const int half  = lane >> 4;          // sample within the warp
    const int lh    = lane & 15;          // lane within half-warp
    const int s     = gwarp * 2 + half;   // batch sample id
    if (s >= BATCH) return;

    // 20 indices per half-warp: lanes 0..15 hold fields 0..15,
    // lanes 0..3 additionally hold fields 16..19.
    const int* xrow = x + s * NUM_FIELDS;
    int xi0 = __ldg(xrow + lh);                                    // fields 0..15
    int xi1 = (lh < NUM_FIELDS - 16) ? __ldg(xrow + 16 + lh) : 0;  // fields 16..19

    float4 sv = make_float4(0.f, 0.f, 0.f, 0.f);   // partial of sum_f V[f]
    float  sq = 0.f;                               // partial of sum V^2

    // ---- Burst 1: fields 0..9 ----
    float4 g1[10];
    #pragma unroll
    for (int f = 0; f < 10; ++f) {
        const int idx = __shfl_sync(0xffffffffu, xi0, f, 16);
        const float4* row = reinterpret_cast<const float4*>(
            emb + ((size_t)f * NUM_FEATURES + (size_t)idx) * LATENT_DIM);
        g1[f] = __ldg(row + lh);
    }
    #pragma unroll
    for (int f = 0; f < 10; ++f) {
        const float4 v = g1[f];
        sv.x += v.x;  sv.y += v.y;  sv.z += v.z;  sv.w += v.w;
        sq = fmaf(v.x, v.x, sq);  sq = fmaf(v.y, v.y, sq);
        sq = fmaf(v.z, v.z, sq);  sq = fmaf(v.w, v.w, sq);
    }

    // Prevent ptxas from hoisting burst-2 LDGs above burst-1 consumption.
    asm volatile("" ::: "memory");

    // ---- Burst 2: fields 10..19 ----
    float4 g2[10];
    #pragma unroll
    for (int f = 10; f < NUM_FIELDS; ++f) {
        int idx;
        if (f < 16) idx = __shfl_sync(0xffffffffu, xi0, f, 16);
        else        idx = __shfl_sync(0xffffffffu, xi1, f - 16, 16);
        const float4* row = reinterpret_cast<const float4*>(
            emb + ((size_t)f * NUM_FEATURES + (size_t)idx) * LATENT_DIM);
        g2[f - 10] = __ldg(row + lh);
    }
    #pragma unroll
    for (int f = 0; f < 10; ++f) {
        const float4 v = g2[f];
        sv.x += v.x;  sv.y += v.y;  sv.z += v.z;  sv.w += v.w;
        sq = fmaf(v.x, v.x, sq);  sq = fmaf(v.y, v.y, sq);
        sq = fmaf(v.z, v.z, sq);  sq = fmaf(v.w, v.w, sq);
    }

    float part = fmaf(sv.x, sv.x, fmaf(sv.y, sv.y,
                 fmaf(sv.z, sv.z, sv.w * sv.w))) - sq;
    int   lin  = xi0 + xi1;

    // Reduce within the 16-lane half-warp.
    #pragma unroll
    for (int o = 8; o > 0; o >>= 1) {
        part += __shfl_xor_sync(0xffffffffu, part, o);
        lin  += __shfl_xor_sync(0xffffffffu, lin,  o);
    }

    if (lh == 0)
        out[s] = (float)lin + 0.5f * part;
}

extern "C" void kernel_launch(void* const* d_in, const int* in_sizes, int n_in,
                              void* d_out, int out_size)
{
    const int*   x   = (const int*)d_in[0];     // (16384, 20) int32
    // d_in[1] = field_indices (arange(20)) — identity, unused
    const float* emb = (const float*)d_in[2];   // (20, 100000, 64) fp32
    float*       out = (float*)d_out;           // (16384,) fp32

    const int threads = 256;                    // 8 warps = 16 samples / block
    const int warps   = (BATCH + 1) / 2;        // 8192 warps
    const int blocks  = (warps * 32 + threads - 1) / threads;  // 1024
    ffm_kernel<<<blocks, threads>>>(x, emb, out);
}